// round 16
// baseline (speedup 1.0000x reference)
#include <cuda_runtime.h>

// ---------------- fixed problem shapes ----------------
#define NB      64
#define LG      3000
#define LL      2998
#define NNODES  50000
#define NEDGES  800000
#define NE2     (NEDGES + NNODES)
#define KTOT    560
#define MROWS   (NB * 32)
#define GBLK    592              // 148 SMs x 4 blocks, all resident

// ---------------- scratch (zero-initialized; pipeline self-resets) ------
__device__ float d_Atot[MROWS * KTOT];
__device__ float d_ysum[MROWS * 121];
__device__ float d_deg[NNODES];          // reset in P5 each run
__device__ float d_h[NNODES * 33];
__device__ float d_xpbn[NNODES * 33];
__device__ float d_xlr[NNODES * 264];
__device__ float d_pool[NB * 132];       // reset in P6 each run
__device__ int   d_cnti[NB];             // reset in P6 each run
__device__ int   d_rowcnt[NNODES];       // reset in P3 each run
__device__ int   d_scantmp[NNODES];
__device__ int   d_blocksum[256];
__device__ int   d_boffchunk[256];
__device__ int   d_rowoff[NNODES + 1];
__device__ int   d_cursor[NNODES];
__device__ int   d_csrc[NE2];
__device__ int2  d_cedge[NE2];
// token buckets
__device__ int   d_posg[NB * LG];
__device__ int   d_posl[NB * LL];
__device__ int   d_boffg[NB * 6];
__device__ int   d_boffl[NB * 66];
// grid barrier state (generation-based; replay-safe)
__device__ int          bar_count = 0;
__device__ volatile int bar_gen = 0;

// ---------------- warp sum ----------------
__device__ __forceinline__ float warp_sum(float v) {
    #pragma unroll
    for (int off = 16; off > 0; off >>= 1) v += __shfl_xor_sync(0xffffffffu, v, off);
    return v;
}

__device__ __forceinline__ void gridbar() {
    __syncthreads();
    __threadfence();
    if (threadIdx.x == 0) {
        int g = bar_gen;
        if (atomicAdd(&bar_count, 1) == GBLK - 1) {
            bar_count = 0;
            __threadfence();
            bar_gen = g + 1;
        } else {
            while (bar_gen == g) __nanosleep(64);
        }
    }
    __syncthreads();
}

// ---------------- persistent fused graph chain ----------------
__global__ __launch_bounds__(256, 4)
void k_graph(const float* __restrict__ pro_x,
             const int* __restrict__ esrc, const int* __restrict__ edst,
             const float* __restrict__ pw, const int* __restrict__ batch,
             const float* __restrict__ gw, const float* __restrict__ gcn_b,
             const float* __restrict__ bnm, const float* __restrict__ bnv,
             const float* __restrict__ bnw, const float* __restrict__ bnb,
             const float* __restrict__ wl, const float* __restrict__ wr_,
             const float* __restrict__ att, const float* __restrict__ gat_b,
             int N, int E) {
    __shared__ float sh[11088];   // 44352 B, aliased per phase
    const unsigned F = 0xffffffffu;
    int t = threadIdx.x, warp = t >> 5, lane = t & 31;
    int gtid = blockIdx.x * 256 + t;
    int gstride = GBLK * 256;

    // ===== P0: degcnt (edges) + h = pro_x @ gcn_w.T (tiles) =====
    for (int e = gtid; e < E; e += gstride) {
        int d = edst[e];
        atomicAdd(&d_deg[d], pw[e]);
        atomicAdd(&d_rowcnt[d], 1);
    }
    {
        float* Ws = sh;              // 33*33
        float* xs = sh + 1089;       // 64*33
        int ntile = (N + 63) / 64;
        for (int i = t; i < 1089; i += 256) Ws[i] = gw[i];
        for (int tile = blockIdx.x; tile < ntile; tile += GBLK) {
            int n0 = tile * 64;
            __syncthreads();
            for (int i = t; i < 64 * 33; i += 256) {
                int n = n0 + i / 33;
                xs[i] = (n < N) ? pro_x[n0 * 33 + i] : 0.f;
            }
            __syncthreads();
            for (int idx = t; idx < 64 * 33; idx += 256) {
                int nl = idx / 33, j = idx - nl * 33, n = n0 + nl;
                if (n < N) {
                    float s = 0.f;
                    #pragma unroll
                    for (int c = 0; c < 33; c++) s += xs[nl * 33 + c] * Ws[j * 33 + c];
                    d_h[n * 33 + j] = s;
                }
            }
        }
    }
    gridbar();

    // ===== P1: per-chunk inclusive scan (chunks of 256) =====
    {
        int* shi = (int*)sh;
        int nchunk = (N + 255) / 256;
        for (int c = blockIdx.x; c < nchunk; c += GBLK) {
            __syncthreads();
            int i = c * 256 + t;
            int v = (i < N) ? (d_rowcnt[i] + 1) : 0;
            int x = v;
            #pragma unroll
            for (int off = 1; off < 32; off <<= 1) {
                int y = __shfl_up_sync(F, x, off);
                if (lane >= off) x += y;
            }
            if (lane == 31) shi[warp] = x;
            __syncthreads();
            if (warp == 0 && lane < 8) {
                int y = shi[lane];
                #pragma unroll
                for (int off = 1; off < 8; off <<= 1) {
                    int z = __shfl_up_sync(0xffu, y, off);
                    if (lane >= off) y += z;
                }
                shi[lane] = y;
            }
            __syncthreads();
            int incl = x + (warp > 0 ? shi[warp - 1] : 0);
            if (i < N) d_scantmp[i] = incl;
            if (t == 255) d_blocksum[c] = incl;
        }
    }
    gridbar();

    // ===== P2: scan chunk sums (block 0) =====
    if (blockIdx.x == 0) {
        int* shi = (int*)sh;
        int nchunk = (N + 255) / 256;
        int v = (t < nchunk) ? d_blocksum[t] : 0;
        int x = v;
        #pragma unroll
        for (int off = 1; off < 32; off <<= 1) {
            int y = __shfl_up_sync(F, x, off);
            if (lane >= off) x += y;
        }
        if (lane == 31) shi[warp] = x;
        __syncthreads();
        if (warp == 0 && lane < 8) {
            int y = shi[lane];
            #pragma unroll
            for (int off = 1; off < 8; off <<= 1) {
                int z = __shfl_up_sync(0xffu, y, off);
                if (lane >= off) y += z;
            }
            shi[lane] = y;
        }
        __syncthreads();
        int incl = x + (warp > 0 ? shi[warp - 1] : 0);
        d_boffchunk[t] = incl - v;
    }
    gridbar();

    // ===== P3: rowoff / cursor (+rowcnt reset) =====
    for (int i = gtid; i < N; i += gstride) {
        int v = d_rowcnt[i] + 1;
        d_rowcnt[i] = 0;
        int excl = d_scantmp[i] - v + d_boffchunk[i >> 8];
        d_rowoff[i] = excl;
        d_cursor[i] = excl;
        if (i == N - 1) d_rowoff[N] = excl + v;
    }
    gridbar();

    // ===== P4: CSR fill =====
    {
        int e2 = E + N;
        for (int e = gtid; e < e2; e += gstride) {
            int s, d; float w;
            if (e < E) { s = esrc[e]; d = edst[e]; w = pw[e]; }
            else       { s = d = e - E; w = 1.f; }
            int pos = atomicAdd(&d_cursor[d], 1);
            float nm = rsqrtf(d_deg[s] + 1.f) * w * rsqrtf(d_deg[d] + 1.f);
            d_csrc[pos] = s;
            d_cedge[pos] = make_int2(s, __float_as_int(nm));
        }
    }
    gridbar();

    // ===== P5: GCN gather + bias/relu/BN -> d_xpbn (+deg reset) =====
    {
        float invL = bnw[lane] * rsqrtf(bnv[lane] + 1e-5f);
        float addL = bnb[lane] - bnm[lane] * invL;
        float gbL  = gcn_b[lane];
        float inv32 = bnw[32] * rsqrtf(bnv[32] + 1e-5f);
        float add32 = bnb[32] - bnm[32] * inv32;
        float gb32  = gcn_b[32];
        int gwarp = blockIdx.x * 8 + warp;
        for (int n = gwarp; n < N; n += GBLK * 8) {
            int st = d_rowoff[n], en = d_rowoff[n + 1];
            int cnt = en - st;
            float acc0 = 0.f, acc1 = 0.f;
            for (int base = 0; base < cnt; base += 32) {
                int m = cnt - base; if (m > 32) m = 32;
                int2 ed = make_int2(0, 0);
                if (base + lane < cnt) ed = d_cedge[st + base + lane];
                for (int j = 0; j < m; j++) {
                    int s = __shfl_sync(F, ed.x, j);
                    float nm = __int_as_float(__shfl_sync(F, ed.y, j));
                    const float* hp = &d_h[s * 33];
                    acc0 += nm * hp[lane];
                    if (lane == 0) acc1 += nm * hp[32];
                }
            }
            float v = fmaxf(acc0 + gbL, 0.f);
            d_xpbn[n * 33 + lane] = v * invL + addL;
            if (lane == 0) {
                float v2 = fmaxf(acc1 + gb32, 0.f);
                d_xpbn[n * 33 + 32] = v2 * inv32 + add32;
            }
        }
        for (int i = gtid; i < N; i += gstride) d_deg[i] = 0.f;
    }
    gridbar();

    // ===== P6: xl/xr GEMM (+pool/cnti reset) =====
    {
        float* Ws = sh;            // 272*33 = 8976
        float* xs = sh + 8976;     // 64*33  = 2112
        for (int i = t; i < 272 * 33; i += 256) {
            int j = i / 33, c = i - j * 33;
            float v = 0.f;
            if (j < 132)      v = wl[j * 33 + c];
            else if (j < 264) v = wr_[(j - 132) * 33 + c];
            Ws[i] = v;
        }
        if (blockIdx.x == 0) {
            for (int i = t; i < NB * 132; i += 256) d_pool[i] = 0.f;
            if (t < NB) d_cnti[t] = 0;
        }
        int ntile = (N + 63) / 64;
        int tx = t & 15, ty = t >> 4;
        for (int tile = blockIdx.x; tile < ntile; tile += GBLK) {
            int n0 = tile * 64;
            __syncthreads();
            for (int i = t; i < 64 * 33; i += 256) {
                int n = n0 + i / 33;
                xs[i] = (n < N) ? d_xpbn[n0 * 33 + i] : 0.f;
            }
            __syncthreads();
            #pragma unroll
            for (int half = 0; half < 2; half++) {
                float acc[2][17];
                #pragma unroll
                for (int a = 0; a < 2; a++)
                    #pragma unroll
                    for (int u = 0; u < 17; u++) acc[a][u] = 0.f;
                int nb0 = ty * 4 + half * 2;
                for (int c = 0; c < 33; c++) {
                    float xv0 = xs[(nb0 + 0) * 33 + c];
                    float xv1 = xs[(nb0 + 1) * 33 + c];
                    #pragma unroll
                    for (int u = 0; u < 17; u++) {
                        float wv = Ws[(tx * 17 + u) * 33 + c];
                        acc[0][u] += xv0 * wv;
                        acc[1][u] += xv1 * wv;
                    }
                }
                #pragma unroll
                for (int a = 0; a < 2; a++) {
                    int n = n0 + nb0 + a;
                    if (n < N) {
                        #pragma unroll
                        for (int u = 0; u < 17; u++) {
                            int j = tx * 17 + u;
                            if (j < 264) d_xlr[n * 264 + j] = acc[a][u];
                        }
                    }
                }
            }
        }
    }
    gridbar();

    // ===== P7: GAT (warp per node, lean softmax, fused pool) =====
    {
        int f0 = lane, f1 = lane + 32, f2 = lane + 64, f3 = lane + 96, f4 = lane + 128;
        bool has4 = lane < 4;
        bool h0f2 = lane < 2;
        bool hi = (lane & 16) != 0;
        float a0 = att[f0], a1 = att[f1], a2 = att[f2], a3 = att[f3];
        float a4 = has4 ? att[f4] : 0.f;
        int gwarp = blockIdx.x * 8 + warp;
        for (int n = gwarp; n < N; n += GBLK * 8) {
            const float* xrd = &d_xlr[n * 264 + 132];
            float xr0 = xrd[f0], xr1 = xrd[f1], xr2 = xrd[f2], xr3 = xrd[f3];
            float xr4 = has4 ? xrd[f4] : 0.f;
            float m0 = -1e30f, m1 = -1e30f, l0 = 0.f, l1 = 0.f;
            float acc0 = 0.f, acc1 = 0.f, acc2 = 0.f, acc3 = 0.f, acc4 = 0.f;
            int st = d_rowoff[n], en = d_rowoff[n + 1];
            int cnt = en - st;
            for (int base = 0; base < cnt; base += 32) {
                int mcnt = cnt - base; if (mcnt > 32) mcnt = 32;
                int sl = 0;
                if (base + lane < cnt) sl = d_csrc[st + base + lane];
                for (int j = 0; j < mcnt; j++) {
                    int s = __shfl_sync(F, sl, j);
                    const float* xls = &d_xlr[s * 264];
                    float x0 = xls[f0], x1 = xls[f1], x2 = xls[f2], x3 = xls[f3];
                    float x4 = has4 ? xls[f4] : 0.f;
                    float tv, p0, p1;
                    tv = x0 + xr0; tv = tv > 0.f ? tv : 0.2f * tv; p0 = tv * a0;
                    tv = x1 + xr1; tv = tv > 0.f ? tv : 0.2f * tv; p0 += tv * a1;
                    tv = x2 + xr2; tv = tv > 0.f ? tv : 0.2f * tv;
                    float c2 = tv * a2;
                    p1 = h0f2 ? 0.f : c2;
                    if (h0f2) p0 += c2;
                    tv = x3 + xr3; tv = tv > 0.f ? tv : 0.2f * tv; p1 += tv * a3;
                    tv = x4 + xr4; tv = tv > 0.f ? tv : 0.2f * tv; p1 += tv * a4;
                    p0 += __shfl_xor_sync(F, p0, 16);
                    p1 += __shfl_xor_sync(F, p1, 16);
                    float z = hi ? p1 : p0;
                    z += __shfl_xor_sync(F, z, 8);
                    z += __shfl_xor_sync(F, z, 4);
                    z += __shfl_xor_sync(F, z, 2);
                    z += __shfl_xor_sync(F, z, 1);
                    float zo = __shfl_xor_sync(F, z, 16);
                    float P0 = hi ? zo : z;
                    float P1 = hi ? z : zo;
                    bool g0 = P0 > m0, g1 = P1 > m1;
                    float e0 = __expf(g0 ? (m0 - P0) : (P0 - m0));
                    float e1 = __expf(g1 ? (m1 - P1) : (P1 - m1));
                    float sc0 = g0 ? e0 : 1.f, w0 = g0 ? 1.f : e0;
                    float sc1 = g1 ? e1 : 1.f, w1 = g1 ? 1.f : e1;
                    if (g0) m0 = P0;
                    if (g1) m1 = P1;
                    l0 = l0 * sc0 + w0; l1 = l1 * sc1 + w1;
                    float scf2 = h0f2 ? sc0 : sc1, wf2 = h0f2 ? w0 : w1;
                    acc0 = acc0 * sc0  + w0  * x0;
                    acc1 = acc1 * sc0  + w0  * x1;
                    acc2 = acc2 * scf2 + wf2 * x2;
                    acc3 = acc3 * sc1  + w1  * x3;
                    acc4 = acc4 * sc1  + w1  * x4;
                }
            }
            int g = batch[n];
            float inv0 = 1.f / l0, inv1 = 1.f / l1;
            float o;
            o = fmaxf(acc0 * inv0 + gat_b[f0], 0.f); atomicAdd(&d_pool[g * 132 + f0], o);
            o = fmaxf(acc1 * inv0 + gat_b[f1], 0.f); atomicAdd(&d_pool[g * 132 + f1], o);
            o = fmaxf(acc2 * (h0f2 ? inv0 : inv1) + gat_b[f2], 0.f); atomicAdd(&d_pool[g * 132 + f2], o);
            o = fmaxf(acc3 * inv1 + gat_b[f3], 0.f); atomicAdd(&d_pool[g * 132 + f3], o);
            if (has4) { o = fmaxf(acc4 * inv1 + gat_b[f4], 0.f); atomicAdd(&d_pool[g * 132 + f4], o); }
            if (lane == 0) atomicAdd(&d_cnti[g], 1);
        }
    }
}

// ---------------- token bucketing (merged): grid 128 -------------------
__global__ void k_bucket(const int* __restrict__ rna_l, const int* __restrict__ rna_g) {
    __shared__ int cnt[65];
    __shared__ int cur[65];
    int b = blockIdx.x & 63, which = blockIdx.x >> 6, t = threadIdx.x;
    const int* rna = which ? rna_g : rna_l;
    int L = which ? LG : LL;
    int V = which ? 5 : 65;
    int* pos  = which ? d_posg : d_posl;
    int* boff = which ? (d_boffg + b * 6) : (d_boffl + b * 66);
    for (int i = t; i < V; i += 256) cnt[i] = 0;
    __syncthreads();
    for (int c = t; c < L; c += 256) atomicAdd(&cnt[rna[b * L + c]], 1);
    __syncthreads();
    if (t == 0) {
        int run = 0;
        for (int v = 0; v < V; v++) {
            boff[v] = run;
            cur[v] = run;
            run += cnt[v];
        }
        boff[V] = run;
    }
    __syncthreads();
    for (int c = t; c < L; c += 256) {
        int v = rna[b * L + c];
        int p = atomicAdd(&cur[v], 1);
        pos[b * L + p] = c;
    }
}

// ---------------- A-build, float4-vectorized: grid (64, 4) --------------
__global__ void k_accA(const float* __restrict__ wl_, const float* __restrict__ wg_) {
    int b = blockIdx.x;
    int warp = threadIdx.x >> 5, lane = threadIdx.x & 31;
    int oo = lane >> 1, q = lane & 1;
    if (blockIdx.y < 2) {
        int og = blockIdx.y;
        int o = og * 16 + oo;
        const float4* wb = reinterpret_cast<const float4*>(wl_ + (size_t)o * (LL * 8)) + q;
        const int* posb = d_posl + b * LL;
        for (int v = warp; v < 65; v += 8) {
            int off = d_boffl[b * 66 + v], end = d_boffl[b * 66 + v + 1];
            float4 racc = make_float4(0.f, 0.f, 0.f, 0.f);
            for (int base = off; base < end; base += 32) {
                int m = end - base; if (m > 32) m = 32;
                int pl = (base + lane < end) ? posb[base + lane] : 0;
                for (int j = 0; j < m; j++) {
                    int c = __shfl_sync(0xffffffffu, pl, j);
                    float4 wv = wb[c * 2];
                    racc.x += wv.x; racc.y += wv.y; racc.z += wv.z; racc.w += wv.w;
                }
            }
            *reinterpret_cast<float4*>(&d_Atot[(b * 32 + o) * KTOT + 40 + v * 8 + q * 4]) = racc;
        }
    } else {
        __shared__ float4 part[8 * 5 * 32];
        int og = blockIdx.y - 2;
        int o = og * 16 + oo;
        const float4* wb = reinterpret_cast<const float4*>(wg_ + (size_t)o * (LG * 8)) + q;
        const int* posb = d_posg + b * LG;
        for (int v = 0; v < 5; v++) {
            int off = d_boffg[b * 6 + v], end = d_boffg[b * 6 + v + 1];
            int m = end - off;
            int s0 = off + (m * warp) / 8;
            int s1 = off + (m * (warp + 1)) / 8;
            float4 racc = make_float4(0.f, 0.f, 0.f, 0.f);
            for (int base = s0; base < s1; base += 32) {
                int mm = s1 - base; if (mm > 32) mm = 32;
                int pl = (base + lane < s1) ? posb[base + lane] : 0;
                for (int j = 0; j < mm; j++) {
                    int c = __shfl_sync(0xffffffffu, pl, j);
                    float4 wv = wb[c * 2];
                    racc.x += wv.x; racc.y += wv.y; racc.z += wv.z; racc.w += wv.w;
                }
            }
            part[(warp * 5 + v) * 32 + lane] = racc;
        }
        __syncthreads();
        int t = threadIdx.x;
        if (t < 160) {
            int v = t >> 5, ln = t & 31;
            float4 s = make_float4(0.f, 0.f, 0.f, 0.f);
            #pragma unroll
            for (int wp = 0; wp < 8; wp++) {
                float4 p = part[(wp * 5 + v) * 32 + ln];
                s.x += p.x; s.y += p.y; s.z += p.z; s.w += p.w;
            }
            int oo2 = ln >> 1, q2 = ln & 1;
            *reinterpret_cast<float4*>(&d_Atot[(b * 32 + og * 16 + oo2) * KTOT + v * 8 + q2 * 4]) = s;
        }
    }
}

// ---------------- GEMM: ysum = Atot x B(emb) ----------------
__global__ void k_gemm_ysum(const float* __restrict__ emb1, const float* __restrict__ emb2,
                            const float* __restrict__ c1b, const float* __restrict__ c2b) {
    __shared__ float Bs[80 * 121];
    __shared__ float As[8 * 80];
    int t = threadIdx.x;
    int rowbase = blockIdx.x * 8;
    int r = t >> 5, lane = t & 31;
    float a0 = 0.f, a1 = 0.f, a2 = 0.f, a3 = 0.f;
    for (int kc = 0; kc < 7; kc++) {
        for (int i = t; i < 640; i += 256)
            As[i] = d_Atot[(rowbase + i / 80) * KTOT + kc * 80 + (i % 80)];
        for (int i = t; i < 80 * 121; i += 256) {
            int row = kc * 80 + i / 121, l = i % 121;
            float v;
            if (row < 40)  v = emb1[(row >> 3) * 128 + l + (row & 7)];
            else { int rr = row - 40; v = emb2[(rr >> 3) * 128 + l + (rr & 7)]; }
            Bs[i] = v;
        }
        __syncthreads();
        #pragma unroll 8
        for (int kk = 0; kk < 80; kk++) {
            float a = As[r * 80 + kk];
            const float* bp = &Bs[kk * 121];
            a0 += a * bp[lane];
            a1 += a * bp[lane + 32];
            a2 += a * bp[lane + 64];
            if (lane < 25) a3 += a * bp[lane + 96];
        }
        __syncthreads();
    }
    int row = rowbase + r, o = row & 31;
    float bias = c1b[o] + c2b[o];
    float* yp = &d_ysum[row * 121];
    yp[lane]      = 0.5f * (a0 + bias);
    yp[lane + 32] = 0.5f * (a1 + bias);
    yp[lane + 64] = 0.5f * (a2 + bias);
    if (lane < 25) yp[lane + 96] = 0.5f * (a3 + bias);
}

// ---------------- xc_rna -> out[0:8192] ----
__global__ void k_xc(const float* __restrict__ w, const float* __restrict__ bias,
                     float* __restrict__ out) {
    __shared__ float ys[3872];
    int jt = blockIdx.x & 15, bt = blockIdx.x >> 4;
    int t = threadIdx.x, warp = t >> 5, lane = t & 31;
    int j = jt * 8 + warp;
    const float* wr = &w[j * 3872];
    for (int bi = 0; bi < 8; bi++) {
        int b = bt * 8 + bi;
        __syncthreads();
        for (int i = t; i < 3872; i += 256) ys[i] = d_ysum[b * 3872 + i];
        __syncthreads();
        float s = 0.f;
        for (int i = lane; i < 3872; i += 32) s += ys[i] * wr[i];
        s = warp_sum(s);
        if (lane == 0) out[b * 128 + j] = s + bias[j];
    }
}

// ---------------- MLP head (warp per output) ----------------
__global__ void k_mlp(const float* __restrict__ w1, const float* __restrict__ b1,
                      const float* __restrict__ w2, const float* __restrict__ b2,
                      float* __restrict__ out) {
    __shared__ float xp[132];
    __shared__ float z[1024];
    int g = blockIdx.x, t = threadIdx.x, warp = t >> 5, lane = t & 31;
    if (t < 132) xp[t] = d_pool[g * 132 + t] / fmaxf((float)d_cnti[g], 1.0f);
    __syncthreads();
    for (int u = warp; u < 1024; u += 8) {
        const float* wr = &w1[u * 132];
        float a = 0.f;
        for (int i = lane; i < 132; i += 32) a += xp[i] * wr[i];
        a = warp_sum(a);
        if (lane == 0) z[u] = fmaxf(a + b1[u], 0.f);
    }
    __syncthreads();
    for (int u = warp; u < 128; u += 8) {
        const float* wr = &w2[u * 1024];
        float a = 0.f;
        for (int i = lane; i < 1024; i += 32) a += z[i] * wr[i];
        a = warp_sum(a);
        if (lane == 0) out[8192 + g * 128 + u] = a + b2[u];
    }
}

// ---------------- host launcher ----------------
extern "C" void kernel_launch(void* const* d_in, const int* in_sizes, int n_in,
                              void* d_out, int out_size) {
    const int*   global_rna = (const int*)d_in[0];
    const int*   local_rna  = (const int*)d_in[1];
    const float* pro_x      = (const float*)d_in[2];
    const int*   edge_index = (const int*)d_in[3];
    const float* pro_weight = (const float*)d_in[4];
    const int*   pro_batch  = (const int*)d_in[5];
    const float* emb1       = (const float*)d_in[6];
    const float* emb2       = (const float*)d_in[7];
    const float* conv1_w    = (const float*)d_in[8];
    const float* conv1_b    = (const float*)d_in[9];
    const float* conv2_w    = (const float*)d_in[10];
    const float* conv2_b    = (const float*)d_in[11];
    const float* fc_xr_w    = (const float*)d_in[12];
    const float* fc_xr_b    = (const float*)d_in[13];
    const float* gcn_w      = (const float*)d_in[14];
    const float* gcn_b      = (const float*)d_in[15];
    const float* bn_mean    = (const float*)d_in[16];
    const float* bn_var     = (const float*)d_in[17];
    const float* bn_weight  = (const float*)d_in[18];
    const float* bn_bias    = (const float*)d_in[19];
    const float* gat_wl     = (const float*)d_in[20];
    const float* gat_wr     = (const float*)d_in[21];
    const float* gat_att    = (const float*)d_in[22];
    const float* gat_b      = (const float*)d_in[23];
    const float* fc1_w      = (const float*)d_in[24];
    const float* fc1_b      = (const float*)d_in[25];
    const float* fc2_w      = (const float*)d_in[26];
    const float* fc2_b      = (const float*)d_in[27];
    float* out = (float*)d_out;

    int E  = in_sizes[3] / 2;
    int N  = in_sizes[2] / 33;
    const int* src = edge_index;
    const int* dst = edge_index + E;

    static cudaStream_t s2 = nullptr;
    static cudaEvent_t evFork = nullptr, evJoin = nullptr;
    if (s2 == nullptr) {
        cudaStreamCreateWithFlags(&s2, cudaStreamNonBlocking);
        cudaEventCreateWithFlags(&evFork, cudaEventDisableTiming);
        cudaEventCreateWithFlags(&evJoin, cudaEventDisableTiming);
    }

    // fork: RNA chain on s2, fused graph chain on stream 0
    cudaEventRecord(evFork, 0);
    cudaStreamWaitEvent(s2, evFork, 0);

    // ---- fused graph chain (stream 0, submission 1) ----
    k_graph<<<GBLK, 256>>>(pro_x, src, dst, pro_weight, pro_batch,
                           gcn_w, gcn_b, bn_mean, bn_var, bn_weight, bn_bias,
                           gat_wl, gat_wr, gat_att, gat_b, N, E);

    // ---- RNA chain (s2; submissions 2-5; 4th = k_gemm_ysum profiled) ----
    k_bucket<<<128, 256, 0, s2>>>(local_rna, global_rna);
    k_accA<<<dim3(NB, 4), 256, 0, s2>>>(conv2_w, conv1_w);
    k_gemm_ysum<<<MROWS / 8, 256, 0, s2>>>(emb1, emb2, conv1_b, conv2_b);
    k_xc<<<128, 256, 0, s2>>>(fc_xr_w, fc_xr_b, out);
    cudaEventRecord(evJoin, s2);

    // join, then MLP head
    cudaStreamWaitEvent(0, evJoin, 0);
    k_mlp<<<NB, 256>>>(fc1_w, fc1_b, fc2_w, fc2_b, out);
}

// round 17
// speedup vs baseline: 1.1965x; 1.1965x over previous
#include <cuda_runtime.h>

// ---------------- fixed problem shapes ----------------
#define NB      64
#define LG      3000
#define LL      2998
#define NNODES  50000
#define NEDGES  800000
#define NE2     (NEDGES + NNODES)
#define KTOT    560
#define MROWS   (NB * 32)

// ---------------- scratch (zero-initialized; pipeline self-resets) ------
__device__ float d_Atot[MROWS * KTOT];
__device__ float d_ysum[MROWS * 121];
__device__ float d_deg[NNODES];          // reset by k_gcn_csr each run
__device__ float d_h[NNODES * 33];
__device__ float d_xpbn[NNODES * 33];
__device__ float d_xl[NNODES * 132];     // gathered by GAT (dense, L2-resident)
__device__ float d_xr[NNODES * 132];     // read linearly once per node
__device__ float d_pool[NB * 132];       // reset by k_xlxr each run
__device__ int   d_cnti[NB];             // reset by k_xlxr each run
__device__ int   d_rowcnt[NNODES];       // reset by k_scan23 each run
__device__ int   d_scantmp[NNODES];
__device__ int   d_blocksum[64];
__device__ int   d_rowoff[NNODES + 1];
__device__ int   d_cursor[NNODES];
__device__ int   d_csrc[NE2];
__device__ int2  d_cedge[NE2];
// token buckets
__device__ int   d_posg[NB * LG];
__device__ int   d_posl[NB * LL];
__device__ int   d_boffg[NB * 6];
__device__ int   d_boffl[NB * 66];

// ---------------- warp sum ----------------
__device__ __forceinline__ float warp_sum(float v) {
    #pragma unroll
    for (int off = 16; off > 0; off >>= 1) v += __shfl_xor_sync(0xffffffffu, v, off);
    return v;
}

// ---------------- degree + indegree (accumulate from zero) ---------------
__global__ void k_degcnt(const int* __restrict__ dst, const float* __restrict__ pw, int E) {
    int e = blockIdx.x * blockDim.x + threadIdx.x;
    if (e < E) {
        int d = dst[e];
        atomicAdd(&d_deg[d], pw[e]);
        atomicAdd(&d_rowcnt[d], 1);
    }
}

// ---------------- token bucketing (merged): grid 128 -------------------
__global__ void k_bucket(const int* __restrict__ rna_l, const int* __restrict__ rna_g) {
    __shared__ int cnt[65];
    __shared__ int cur[65];
    int b = blockIdx.x & 63, which = blockIdx.x >> 6, t = threadIdx.x;
    const int* rna = which ? rna_g : rna_l;
    int L = which ? LG : LL;
    int V = which ? 5 : 65;
    int* pos  = which ? d_posg : d_posl;
    int* boff = which ? (d_boffg + b * 6) : (d_boffl + b * 66);
    for (int i = t; i < V; i += 256) cnt[i] = 0;
    __syncthreads();
    for (int c = t; c < L; c += 256) atomicAdd(&cnt[rna[b * L + c]], 1);
    __syncthreads();
    if (t == 0) {
        int run = 0;
        for (int v = 0; v < V; v++) {
            boff[v] = run;
            cur[v] = run;
            run += cnt[v];
        }
        boff[V] = run;
    }
    __syncthreads();
    for (int c = t; c < L; c += 256) {
        int v = rna[b * L + c];
        int p = atomicAdd(&cur[v], 1);
        pos[b * L + p] = c;
    }
}

// ---------------- A-build, float4-vectorized: grid (64, 4) --------------
__global__ void k_accA(const float* __restrict__ wl_, const float* __restrict__ wg_) {
    int b = blockIdx.x;
    int warp = threadIdx.x >> 5, lane = threadIdx.x & 31;
    int oo = lane >> 1, q = lane & 1;
    if (blockIdx.y < 2) {
        int og = blockIdx.y;
        int o = og * 16 + oo;
        const float4* wb = reinterpret_cast<const float4*>(wl_ + (size_t)o * (LL * 8)) + q;
        const int* posb = d_posl + b * LL;
        for (int v = warp; v < 65; v += 8) {
            int off = d_boffl[b * 66 + v], end = d_boffl[b * 66 + v + 1];
            float4 racc = make_float4(0.f, 0.f, 0.f, 0.f);
            for (int base = off; base < end; base += 32) {
                int m = end - base; if (m > 32) m = 32;
                int pl = (base + lane < end) ? posb[base + lane] : 0;
                for (int j = 0; j < m; j++) {
                    int c = __shfl_sync(0xffffffffu, pl, j);
                    float4 wv = wb[c * 2];
                    racc.x += wv.x; racc.y += wv.y; racc.z += wv.z; racc.w += wv.w;
                }
            }
            *reinterpret_cast<float4*>(&d_Atot[(b * 32 + o) * KTOT + 40 + v * 8 + q * 4]) = racc;
        }
    } else {
        __shared__ float4 part[8 * 5 * 32];
        int og = blockIdx.y - 2;
        int o = og * 16 + oo;
        const float4* wb = reinterpret_cast<const float4*>(wg_ + (size_t)o * (LG * 8)) + q;
        const int* posb = d_posg + b * LG;
        for (int v = 0; v < 5; v++) {
            int off = d_boffg[b * 6 + v], end = d_boffg[b * 6 + v + 1];
            int m = end - off;
            int s0 = off + (m * warp) / 8;
            int s1 = off + (m * (warp + 1)) / 8;
            float4 racc = make_float4(0.f, 0.f, 0.f, 0.f);
            for (int base = s0; base < s1; base += 32) {
                int mm = s1 - base; if (mm > 32) mm = 32;
                int pl = (base + lane < s1) ? posb[base + lane] : 0;
                for (int j = 0; j < mm; j++) {
                    int c = __shfl_sync(0xffffffffu, pl, j);
                    float4 wv = wb[c * 2];
                    racc.x += wv.x; racc.y += wv.y; racc.z += wv.z; racc.w += wv.w;
                }
            }
            part[(warp * 5 + v) * 32 + lane] = racc;
        }
        __syncthreads();
        int t = threadIdx.x;
        if (t < 160) {
            int v = t >> 5, ln = t & 31;
            float4 s = make_float4(0.f, 0.f, 0.f, 0.f);
            #pragma unroll
            for (int wp = 0; wp < 8; wp++) {
                float4 p = part[(wp * 5 + v) * 32 + ln];
                s.x += p.x; s.y += p.y; s.z += p.z; s.w += p.w;
            }
            int oo2 = ln >> 1, q2 = ln & 1;
            *reinterpret_cast<float4*>(&d_Atot[(b * 32 + og * 16 + oo2) * KTOT + v * 8 + q2 * 4]) = s;
        }
    }
}

// ---------------- scan stage 1 (counts include implicit self-loop) -------
__global__ void k_scan1(int N) {
    int i = blockIdx.x * 1024 + threadIdx.x;
    int lane = threadIdx.x & 31, wid = threadIdx.x >> 5;
    int v = (i < N) ? (d_rowcnt[i] + 1) : 0;
    int x = v;
    #pragma unroll
    for (int off = 1; off < 32; off <<= 1) {
        int y = __shfl_up_sync(0xffffffffu, x, off);
        if (lane >= off) x += y;
    }
    __shared__ int ws[32];
    if (lane == 31) ws[wid] = x;
    __syncthreads();
    if (wid == 0) {
        int y = ws[lane];
        #pragma unroll
        for (int off = 1; off < 32; off <<= 1) {
            int z = __shfl_up_sync(0xffffffffu, y, off);
            if (lane >= off) y += z;
        }
        ws[lane] = y;
    }
    __syncthreads();
    int incl = x + (wid > 0 ? ws[wid - 1] : 0);
    if (i < N) d_scantmp[i] = incl;
    if (threadIdx.x == 1023) d_blocksum[blockIdx.x] = incl;
}

// ---------------- scan stages 2+3 merged (+rowcnt reset) ----------------
__global__ void k_scan23(int N) {
    __shared__ int boff_s;
    int i = blockIdx.x * 256 + threadIdx.x;
    int bk = (blockIdx.x * 256) >> 10;
    if (threadIdx.x < 32) {
        int lane = threadIdx.x;
        int s = 0;
        if (lane < bk)      s += d_blocksum[lane];
        if (lane + 32 < bk) s += d_blocksum[lane + 32];
        #pragma unroll
        for (int off = 16; off > 0; off >>= 1) s += __shfl_xor_sync(0xffffffffu, s, off);
        if (lane == 0) boff_s = s;
    }
    __syncthreads();
    if (i < N) {
        int v = d_rowcnt[i] + 1;
        d_rowcnt[i] = 0;
        int excl = d_scantmp[i] - v + boff_s;
        d_rowoff[i] = excl;
        d_cursor[i] = excl;
        if (i == N - 1) d_rowoff[N] = excl + v;
    }
}

// ---------------- CSR fill (deg baseline +1 for self-loop) ---------------
__global__ void k_csr_fill(const int* __restrict__ src, const int* __restrict__ dst,
                           const float* __restrict__ pw, int E, int e2) {
    int e = blockIdx.x * blockDim.x + threadIdx.x;
    if (e >= e2) return;
    int s, d; float w;
    if (e < E) { s = src[e]; d = dst[e]; w = pw[e]; }
    else       { s = d = e - E; w = 1.f; }
    int pos = atomicAdd(&d_cursor[d], 1);
    float nm = rsqrtf(d_deg[s] + 1.f) * w * rsqrtf(d_deg[d] + 1.f);
    d_csrc[pos] = s;
    d_cedge[pos] = make_int2(s, __float_as_int(nm));
}

// ---------------- GEMM: ysum = Atot x B(emb) ----------------
__global__ void k_gemm_ysum(const float* __restrict__ emb1, const float* __restrict__ emb2,
                            const float* __restrict__ c1b, const float* __restrict__ c2b) {
    __shared__ float Bs[80 * 121];
    __shared__ float As[8 * 80];
    int t = threadIdx.x;
    int rowbase = blockIdx.x * 8;
    int r = t >> 5, lane = t & 31;
    float a0 = 0.f, a1 = 0.f, a2 = 0.f, a3 = 0.f;
    for (int kc = 0; kc < 7; kc++) {
        for (int i = t; i < 640; i += 256)
            As[i] = d_Atot[(rowbase + i / 80) * KTOT + kc * 80 + (i % 80)];
        for (int i = t; i < 80 * 121; i += 256) {
            int row = kc * 80 + i / 121, l = i % 121;
            float v;
            if (row < 40)  v = emb1[(row >> 3) * 128 + l + (row & 7)];
            else { int rr = row - 40; v = emb2[(rr >> 3) * 128 + l + (rr & 7)]; }
            Bs[i] = v;
        }
        __syncthreads();
        #pragma unroll 8
        for (int kk = 0; kk < 80; kk++) {
            float a = As[r * 80 + kk];
            const float* bp = &Bs[kk * 121];
            a0 += a * bp[lane];
            a1 += a * bp[lane + 32];
            a2 += a * bp[lane + 64];
            if (lane < 25) a3 += a * bp[lane + 96];
        }
        __syncthreads();
    }
    int row = rowbase + r, o = row & 31;
    float bias = c1b[o] + c2b[o];
    float* yp = &d_ysum[row * 121];
    yp[lane]      = 0.5f * (a0 + bias);
    yp[lane + 32] = 0.5f * (a1 + bias);
    yp[lane + 64] = 0.5f * (a2 + bias);
    if (lane < 25) yp[lane + 96] = 0.5f * (a3 + bias);
}

// ---------------- xc_rna -> out[0:8192] ----
__global__ void k_xc(const float* __restrict__ w, const float* __restrict__ bias,
                     float* __restrict__ out) {
    __shared__ float ys[3872];
    int jt = blockIdx.x & 15, bt = blockIdx.x >> 4;
    int t = threadIdx.x, warp = t >> 5, lane = t & 31;
    int j = jt * 8 + warp;
    const float* wr = &w[j * 3872];
    for (int bi = 0; bi < 8; bi++) {
        int b = bt * 8 + bi;
        __syncthreads();
        for (int i = t; i < 3872; i += 256) ys[i] = d_ysum[b * 3872 + i];
        __syncthreads();
        float s = 0.f;
        for (int i = lane; i < 3872; i += 32) s += ys[i] * wr[i];
        s = warp_sum(s);
        if (lane == 0) out[b * 128 + j] = s + bias[j];
    }
}

// ---------------- h = pro_x @ gcn_w.T ----------------
__global__ void k_h(const float* __restrict__ x, const float* __restrict__ gw, int N) {
    __shared__ float Ws[33 * 33];
    __shared__ float xs[64 * 33];
    int t = threadIdx.x, n0 = blockIdx.x * 64;
    for (int i = t; i < 1089; i += 256) Ws[i] = gw[i];
    for (int i = t; i < 64 * 33; i += 256) {
        int n = n0 + i / 33;
        xs[i] = (n < N) ? x[n0 * 33 + i] : 0.f;
    }
    __syncthreads();
    for (int idx = t; idx < 64 * 33; idx += 256) {
        int nl = idx / 33, j = idx - nl * 33, n = n0 + nl;
        if (n < N) {
            float s = 0.f;
            #pragma unroll
            for (int c = 0; c < 33; c++) s += xs[nl * 33 + c] * Ws[j * 33 + c];
            d_h[n * 33 + j] = s;
        }
    }
}

// ---------------- GCN gather + bias/relu/BN (+deg reset) ----------------
__global__ void k_gcn_csr(const float* __restrict__ gcn_b, const float* __restrict__ bnm,
                          const float* __restrict__ bnv, const float* __restrict__ bnw,
                          const float* __restrict__ bnb, int N) {
    {
        int base = blockIdx.x * 8 + (threadIdx.x >> 5);
        int idx = base * 32 + (threadIdx.x & 31);
        if (idx < NNODES) d_deg[idx] = 0.f;
    }
    int wid = (blockIdx.x * blockDim.x + threadIdx.x) >> 5;
    int lane = threadIdx.x & 31;
    if (wid >= N) return;
    int st = d_rowoff[wid], en = d_rowoff[wid + 1];
    int cnt = en - st;
    float acc0 = 0.f, acc1 = 0.f;
    for (int base = 0; base < cnt; base += 32) {
        int m = cnt - base; if (m > 32) m = 32;
        int2 ed = make_int2(0, 0);
        if (base + lane < cnt) ed = d_cedge[st + base + lane];
        for (int j = 0; j < m; j++) {
            int s = __shfl_sync(0xffffffffu, ed.x, j);
            float nm = __int_as_float(__shfl_sync(0xffffffffu, ed.y, j));
            const float* hp = &d_h[s * 33];
            acc0 += nm * hp[lane];
            if (lane == 0) acc1 += nm * hp[32];
        }
    }
    float v = fmaxf(acc0 + gcn_b[lane], 0.f);
    float inv = bnw[lane] * rsqrtf(bnv[lane] + 1e-5f);
    d_xpbn[wid * 33 + lane] = v * inv + (bnb[lane] - bnm[lane] * inv);
    if (lane == 0) {
        float v2 = fmaxf(acc1 + gcn_b[32], 0.f);
        float inv2 = bnw[32] * rsqrtf(bnv[32] + 1e-5f);
        d_xpbn[wid * 33 + 32] = v2 * inv2 + (bnb[32] - bnm[32] * inv2);
    }
}

// ---------------- xl / xr = xp_bn @ {wl,wr}.T (+pool init; split stores) -
__global__ void k_xlxr(const float* __restrict__ wl, const float* __restrict__ wr_, int N) {
    __shared__ float Ws[272 * 33];
    __shared__ float xs[64 * 33];
    int t = threadIdx.x, n0 = blockIdx.x * 64;
    if (blockIdx.x == 0) {
        for (int i = t; i < NB * 132; i += 256) d_pool[i] = 0.f;
        if (t < NB) d_cnti[t] = 0;
    }
    for (int i = t; i < 272 * 33; i += 256) {
        int j = i / 33, c = i - j * 33;
        float v = 0.f;
        if (j < 132)      v = wl[j * 33 + c];
        else if (j < 264) v = wr_[(j - 132) * 33 + c];
        Ws[i] = v;
    }
    for (int i = t; i < 64 * 33; i += 256) {
        int n = n0 + i / 33;
        xs[i] = (n < N) ? d_xpbn[n0 * 33 + i] : 0.f;
    }
    __syncthreads();
    int tx = t & 15, ty = t >> 4;
    float acc[4][17];
    #pragma unroll
    for (int a = 0; a < 4; a++)
        #pragma unroll
        for (int u = 0; u < 17; u++) acc[a][u] = 0.f;
    for (int c = 0; c < 33; c++) {
        float xv0 = xs[(ty * 4 + 0) * 33 + c];
        float xv1 = xs[(ty * 4 + 1) * 33 + c];
        float xv2 = xs[(ty * 4 + 2) * 33 + c];
        float xv3 = xs[(ty * 4 + 3) * 33 + c];
        #pragma unroll
        for (int u = 0; u < 17; u++) {
            float wv = Ws[(tx * 17 + u) * 33 + c];
            acc[0][u] += xv0 * wv; acc[1][u] += xv1 * wv;
            acc[2][u] += xv2 * wv; acc[3][u] += xv3 * wv;
        }
    }
    #pragma unroll
    for (int a = 0; a < 4; a++) {
        int n = n0 + ty * 4 + a;
        if (n < N) {
            #pragma unroll
            for (int u = 0; u < 17; u++) {
                int j = tx * 17 + u;
                if (j < 132)      d_xl[n * 132 + j] = acc[a][u];
                else if (j < 264) d_xr[n * 132 + (j - 132)] = acc[a][u];
            }
        }
    }
}

// ---------------- GAT: warp per node, dense-xl gather, lean softmax ------
__global__ void k_gat_csr(const float* __restrict__ att, const float* __restrict__ gat_b,
                          const int* __restrict__ batch, int N) {
    const unsigned F = 0xffffffffu;
    int wid = (blockIdx.x * blockDim.x + threadIdx.x) >> 5;
    int lane = threadIdx.x & 31;
    if (wid >= N) return;
    int n = wid;
    int f0 = lane, f1 = lane + 32, f2 = lane + 64, f3 = lane + 96, f4 = lane + 128;
    bool has4 = lane < 4;
    bool h0f2 = lane < 2;
    bool hi = (lane & 16) != 0;
    const float* xrd = &d_xr[n * 132];
    float xr0 = xrd[f0], xr1 = xrd[f1], xr2 = xrd[f2], xr3 = xrd[f3];
    float xr4 = has4 ? xrd[f4] : 0.f;
    float a0 = att[f0], a1 = att[f1], a2 = att[f2], a3 = att[f3];
    float a4 = has4 ? att[f4] : 0.f;
    float m0 = -1e30f, m1 = -1e30f, l0 = 0.f, l1 = 0.f;
    float acc0 = 0.f, acc1 = 0.f, acc2 = 0.f, acc3 = 0.f, acc4 = 0.f;
    int st = d_rowoff[n], en = d_rowoff[n + 1];
    int cnt = en - st;
    for (int base = 0; base < cnt; base += 32) {
        int mcnt = cnt - base; if (mcnt > 32) mcnt = 32;
        int sl = 0;
        if (base + lane < cnt) sl = d_csrc[st + base + lane];
        for (int j = 0; j < mcnt; j++) {
            int s = __shfl_sync(F, sl, j);
            const float* xls = &d_xl[s * 132];
            float x0 = xls[f0], x1 = xls[f1], x2 = xls[f2], x3 = xls[f3];
            float x4 = has4 ? xls[f4] : 0.f;
            float t, p0, p1;
            t = x0 + xr0; t = t > 0.f ? t : 0.2f * t; p0 = t * a0;
            t = x1 + xr1; t = t > 0.f ? t : 0.2f * t; p0 += t * a1;
            t = x2 + xr2; t = t > 0.f ? t : 0.2f * t;
            float c2 = t * a2;
            p1 = h0f2 ? 0.f : c2;
            if (h0f2) p0 += c2;
            t = x3 + xr3; t = t > 0.f ? t : 0.2f * t; p1 += t * a3;
            t = x4 + xr4; t = t > 0.f ? t : 0.2f * t; p1 += t * a4;
            p0 += __shfl_xor_sync(F, p0, 16);
            p1 += __shfl_xor_sync(F, p1, 16);
            float z = hi ? p1 : p0;
            z += __shfl_xor_sync(F, z, 8);
            z += __shfl_xor_sync(F, z, 4);
            z += __shfl_xor_sync(F, z, 2);
            z += __shfl_xor_sync(F, z, 1);
            float zo = __shfl_xor_sync(F, z, 16);
            float P0 = hi ? zo : z;
            float P1 = hi ? z : zo;
            bool g0 = P0 > m0, g1 = P1 > m1;
            float e0 = __expf(g0 ? (m0 - P0) : (P0 - m0));
            float e1 = __expf(g1 ? (m1 - P1) : (P1 - m1));
            float sc0 = g0 ? e0 : 1.f, w0 = g0 ? 1.f : e0;
            float sc1 = g1 ? e1 : 1.f, w1 = g1 ? 1.f : e1;
            if (g0) m0 = P0;
            if (g1) m1 = P1;
            l0 = l0 * sc0 + w0; l1 = l1 * sc1 + w1;
            float scf2 = h0f2 ? sc0 : sc1, wf2 = h0f2 ? w0 : w1;
            acc0 = acc0 * sc0  + w0  * x0;
            acc1 = acc1 * sc0  + w0  * x1;
            acc2 = acc2 * scf2 + wf2 * x2;
            acc3 = acc3 * sc1  + w1  * x3;
            acc4 = acc4 * sc1  + w1  * x4;
        }
    }
    int g = batch[n];
    float inv0 = 1.f / l0, inv1 = 1.f / l1;
    float o;
    o = fmaxf(acc0 * inv0 + gat_b[f0], 0.f); atomicAdd(&d_pool[g * 132 + f0], o);
    o = fmaxf(acc1 * inv0 + gat_b[f1], 0.f); atomicAdd(&d_pool[g * 132 + f1], o);
    o = fmaxf(acc2 * (h0f2 ? inv0 : inv1) + gat_b[f2], 0.f); atomicAdd(&d_pool[g * 132 + f2], o);
    o = fmaxf(acc3 * inv1 + gat_b[f3], 0.f); atomicAdd(&d_pool[g * 132 + f3], o);
    if (has4) { o = fmaxf(acc4 * inv1 + gat_b[f4], 0.f); atomicAdd(&d_pool[g * 132 + f4], o); }
    if (lane == 0) atomicAdd(&d_cnti[g], 1);
}

// ---------------- MLP head (warp per output) ----------------
__global__ void k_mlp(const float* __restrict__ w1, const float* __restrict__ b1,
                      const float* __restrict__ w2, const float* __restrict__ b2,
                      float* __restrict__ out) {
    __shared__ float xp[132];
    __shared__ float z[1024];
    int g = blockIdx.x, t = threadIdx.x, warp = t >> 5, lane = t & 31;
    if (t < 132) xp[t] = d_pool[g * 132 + t] / fmaxf((float)d_cnti[g], 1.0f);
    __syncthreads();
    for (int u = warp; u < 1024; u += 8) {
        const float* wr = &w1[u * 132];
        float a = 0.f;
        for (int i = lane; i < 132; i += 32) a += xp[i] * wr[i];
        a = warp_sum(a);
        if (lane == 0) z[u] = fmaxf(a + b1[u], 0.f);
    }
    __syncthreads();
    for (int u = warp; u < 128; u += 8) {
        const float* wr = &w2[u * 1024];
        float a = 0.f;
        for (int i = lane; i < 1024; i += 32) a += z[i] * wr[i];
        a = warp_sum(a);
        if (lane == 0) out[8192 + g * 128 + u] = a + b2[u];
    }
}

// ---------------- host launcher (round-14 structure) ----------------
extern "C" void kernel_launch(void* const* d_in, const int* in_sizes, int n_in,
                              void* d_out, int out_size) {
    const int*   global_rna = (const int*)d_in[0];
    const int*   local_rna  = (const int*)d_in[1];
    const float* pro_x      = (const float*)d_in[2];
    const int*   edge_index = (const int*)d_in[3];
    const float* pro_weight = (const float*)d_in[4];
    const int*   pro_batch  = (const int*)d_in[5];
    const float* emb1       = (const float*)d_in[6];
    const float* emb2       = (const float*)d_in[7];
    const float* conv1_w    = (const float*)d_in[8];
    const float* conv1_b    = (const float*)d_in[9];
    const float* conv2_w    = (const float*)d_in[10];
    const float* conv2_b    = (const float*)d_in[11];
    const float* fc_xr_w    = (const float*)d_in[12];
    const float* fc_xr_b    = (const float*)d_in[13];
    const float* gcn_w      = (const float*)d_in[14];
    const float* gcn_b      = (const float*)d_in[15];
    const float* bn_mean    = (const float*)d_in[16];
    const float* bn_var     = (const float*)d_in[17];
    const float* bn_weight  = (const float*)d_in[18];
    const float* bn_bias    = (const float*)d_in[19];
    const float* gat_wl     = (const float*)d_in[20];
    const float* gat_wr     = (const float*)d_in[21];
    const float* gat_att    = (const float*)d_in[22];
    const float* gat_b      = (const float*)d_in[23];
    const float* fc1_w      = (const float*)d_in[24];
    const float* fc1_b      = (const float*)d_in[25];
    const float* fc2_w      = (const float*)d_in[26];
    const float* fc2_b      = (const float*)d_in[27];
    float* out = (float*)d_out;

    int E  = in_sizes[3] / 2;
    int N  = in_sizes[2] / 33;
    int e2 = E + N;
    const int* src = edge_index;
    const int* dst = edge_index + E;
    int nb = (N + 1023) / 1024;

    static cudaStream_t s2 = nullptr, s3 = nullptr;
    static cudaEvent_t evFork = nullptr, evJoin = nullptr, evH = nullptr;
    if (s2 == nullptr) {
        cudaStreamCreateWithFlags(&s2, cudaStreamNonBlocking);
        cudaStreamCreateWithFlags(&s3, cudaStreamNonBlocking);
        cudaEventCreateWithFlags(&evFork, cudaEventDisableTiming);
        cudaEventCreateWithFlags(&evJoin, cudaEventDisableTiming);
        cudaEventCreateWithFlags(&evH, cudaEventDisableTiming);
    }

    // fork
    cudaEventRecord(evFork, 0);
    cudaStreamWaitEvent(s2, evFork, 0);
    cudaStreamWaitEvent(s3, evFork, 0);

    // ---- RNA chain (s2) ----
    k_bucket<<<128, 256, 0, s2>>>(local_rna, global_rna);
    k_accA<<<dim3(NB, 4), 256, 0, s2>>>(conv2_w, conv1_w);
    k_gemm_ysum<<<MROWS / 8, 256, 0, s2>>>(emb1, emb2, conv1_b, conv2_b);
    k_xc<<<128, 256, 0, s2>>>(fc_xr_w, fc_xr_b, out);
    cudaEventRecord(evJoin, s2);

    // ---- h on s3 (depends only on pro_x) ----
    k_h<<<(N + 63) / 64, 256, 0, s3>>>(pro_x, gcn_w, N);
    cudaEventRecord(evH, s3);

    // ---- graph chain (stream 0) ----
    k_degcnt<<<(E + 255) / 256, 256>>>(dst, pro_weight, E);
    k_scan1<<<nb, 1024>>>(N);
    k_scan23<<<(N + 255) / 256, 256>>>(N);
    k_csr_fill<<<(e2 + 255) / 256, 256>>>(src, dst, pro_weight, E, e2);
    cudaStreamWaitEvent(0, evH, 0);
    k_gcn_csr<<<(N * 32 + 255) / 256, 256>>>(gcn_b, bn_mean, bn_var, bn_weight, bn_bias, N);
    k_xlxr<<<(N + 63) / 64, 256>>>(gat_wl, gat_wr, N);
    k_gat_csr<<<(N * 32 + 255) / 256, 256>>>(gat_att, gat_b, pro_batch, N);

    // join, then MLP head
    cudaStreamWaitEvent(0, evJoin, 0);
    k_mlp<<<NB, 256>>>(fc1_w, fc1_b, fc2_w, fc2_b, out);
}